// round 12
// baseline (speedup 1.0000x reference)
#include <cuda_runtime.h>
#include <cuda_fp16.h>
#include <math.h>
#include <stdint.h>

#define B_ 4
#define N_ 4096
#define IN_DIM 256
#define OUT_DIM 128
#define NROWS (B_ * N_)
#define PADH 72            // k1 smem half pitch (144B rows)
#define TJ2 128            // kAB j-tile
#define NT2 (N_ / TJ2)     // 32 tiles
#define PAD2 136           // kAB smem pitch in halves (272B)
#define PITCH2 272
#define RCTA 128

// Scratch (no cudaMalloc allowed)
__device__ __half g_hT[(size_t)B_ * OUT_DIM * N_];// f16 h^T: [b][d][j]
__device__ float2 g_S [NROWS];                    // (exp(s/2), exp(s/10))
__device__ float2 g_E [NROWS];                    // (exp(d/2), exp(d/10))

// ---------------------------------------------------------------------------
__device__ __forceinline__ uint32_t sm_u32(const void* p) {
    uint32_t a;
    asm("{ .reg .u64 t; cvta.to.shared.u64 t, %1; cvt.u32.u64 %0, t; }"
        : "=r"(a) : "l"(p));
    return a;
}
__device__ __forceinline__ void cp16(uint32_t dst, const void* src) {
    asm volatile("cp.async.cg.shared.global [%0], [%1], 16;"
                 :: "r"(dst), "l"(src));
}
__device__ __forceinline__ void cp_commit() {
    asm volatile("cp.async.commit_group;" ::: "memory");
}
template <int N>
__device__ __forceinline__ void cp_wait() {
    asm volatile("cp.async.wait_group %0;" :: "n"(N) : "memory");
}
__device__ __forceinline__ void ldsm_x4(uint32_t& r0, uint32_t& r1,
                                        uint32_t& r2, uint32_t& r3,
                                        uint32_t addr) {
    asm volatile("ldmatrix.sync.aligned.m8n8.x4.shared.b16 {%0,%1,%2,%3}, [%4];"
                 : "=r"(r0), "=r"(r1), "=r"(r2), "=r"(r3) : "r"(addr));
}
__device__ __forceinline__ void mma16816(float* c,
                                         uint32_t a0, uint32_t a1,
                                         uint32_t a2, uint32_t a3,
                                         uint32_t b0, uint32_t b1) {
    asm volatile("mma.sync.aligned.m16n8k16.row.col.f32.f16.f16.f32 "
                 "{%0,%1,%2,%3},{%4,%5,%6,%7},{%8,%9},{%0,%1,%2,%3};"
                 : "+f"(c[0]), "+f"(c[1]), "+f"(c[2]), "+f"(c[3])
                 : "r"(a0), "r"(a1), "r"(a2), "r"(a3), "r"(b0), "r"(b1));
}

// ---------------------------------------------------------------------------
// k1: hT = W^T x^T via mma.sync f16 (M=d=128, N=j=128/CTA, K=256).
// W transposed to f16 in-prologue (kW folded in). Fused s/d reductions ->
// g_S / g_E exp tables.
// ---------------------------------------------------------------------------
#define WT_PITCH_B 528
#define WT_BYTES   (OUT_DIM * WT_PITCH_B)
#define XS_BYTES   (128 * PADH * 2)
#define K1_DSM     (WT_BYTES + 2 * XS_BYTES)

__global__ void __launch_bounds__(256) k1_gemm(const float* __restrict__ x,
                                               const float* __restrict__ W,
                                               const float* __restrict__ a_src,
                                               const float* __restrict__ a_dst) {
    extern __shared__ __align__(16) char dsm[];
    __shared__ float s_sm[128], d_sm[128];

    const int tid  = threadIdx.x;
    const int wid  = tid >> 5, lane = tid & 31;
    const int j0g  = blockIdx.x * 128;
    const int batch = j0g >> 12;
    const int jloc  = j0g & (N_ - 1);

    if (tid < 128) { s_sm[tid] = 0.f; d_sm[tid] = 0.f; }

    const uint32_t smb = sm_u32(dsm);

    float4 XR[8];
    const int xj = tid >> 4, xk = (tid & 15) << 2;

#define LDG_X(CH)                                                             \
    do {                                                                      \
        _Pragma("unroll")                                                     \
        for (int i = 0; i < 8; i++)                                           \
            XR[i] = *(const float4*)&x[(size_t)(j0g + xj + i * 16) * IN_DIM   \
                                       + (CH) * 64 + xk];                     \
    } while (0)

    LDG_X(0);   // overlap x loads with W transpose below

    // W[k][d] fp32 -> smem WT f16 [d][k] (pitch 528B), via fp32 smem scratch
    {
        float* sx = (float*)(dsm + WT_BYTES);   // 32 x 132 fp32 scratch
        for (int kc0 = 0; kc0 < IN_DIM; kc0 += 32) {
#pragma unroll
            for (int i = 0; i < 4; i++) {
                int f  = tid + 256 * i;
                int kk = f >> 5, d4 = (f & 31) << 2;
                float4 v = *(const float4*)&W[(size_t)(kc0 + kk) * OUT_DIM + d4];
                sx[kk * 132 + d4 + 0] = v.x; sx[kk * 132 + d4 + 1] = v.y;
                sx[kk * 132 + d4 + 2] = v.z; sx[kk * 132 + d4 + 3] = v.w;
            }
            __syncthreads();
            {
                int d = tid >> 1, kh = (tid & 1) << 4;
#pragma unroll
                for (int q = 0; q < 8; q++) {
                    __half2 h = __floats2half2_rn(sx[(kh + 2 * q) * 132 + d],
                                                  sx[(kh + 2 * q + 1) * 132 + d]);
                    *(__half2*)(dsm + d * WT_PITCH_B + (kc0 + kh + 2 * q) * 2) = h;
                }
            }
            __syncthreads();
        }
    }

    const int mh = wid & 1, nq = wid >> 1;
    const uint32_t aoff = (uint32_t)((mh * 64 + (lane & 15)) * WT_PITCH_B
                                     + ((lane >> 4) << 4));
    const uint32_t boff = (uint32_t)((nq * 32 + ((lane >> 4) << 3) + (lane & 7)) * (PADH * 2)
                                     + (((lane >> 3) & 1) << 4));

    float as0[4], as1[4], ad0[4], ad1[4];
#pragma unroll
    for (int mt = 0; mt < 4; mt++) {
        int d0 = mh * 64 + mt * 16 + (lane >> 2);
        as0[mt] = a_src[d0]; as1[mt] = a_src[d0 + 8];
        ad0[mt] = a_dst[d0]; ad1[mt] = a_dst[d0 + 8];
    }

    float c[16][4];
#pragma unroll
    for (int q = 0; q < 16; q++)
        c[q][0] = c[q][1] = c[q][2] = c[q][3] = 0.f;

    for (int ch = 0; ch < 4; ch++) {
        {
            char* xb = dsm + WT_BYTES + (ch & 1) * XS_BYTES;
#pragma unroll
            for (int i = 0; i < 8; i++) {
                __half2 p0 = __floats2half2_rn(XR[i].x, XR[i].y);
                __half2 p1 = __floats2half2_rn(XR[i].z, XR[i].w);
                uint2 u; u.x = *(uint32_t*)&p0; u.y = *(uint32_t*)&p1;
                *(uint2*)(xb + (xj + i * 16) * (PADH * 2) + xk * 2) = u;
            }
        }
        __syncthreads();
        if (ch < 3) LDG_X(ch + 1);

        const uint32_t ab = smb + aoff + ch * 128;
        const uint32_t bb = smb + WT_BYTES + (ch & 1) * XS_BYTES + boff;
#pragma unroll
        for (int ks = 0; ks < 4; ks++) {
            uint32_t b0, b1, b2, b3, b4, b5, b6, b7;
            ldsm_x4(b0, b1, b2, b3, bb + ks * 32);
            ldsm_x4(b4, b5, b6, b7, bb + 16 * (PADH * 2) + ks * 32);
#pragma unroll
            for (int mt = 0; mt < 4; mt++) {
                uint32_t a0, a1, a2, a3;
                ldsm_x4(a0, a1, a2, a3, ab + mt * 16 * WT_PITCH_B + ks * 32);
                mma16816(c[mt * 4 + 0], a0, a1, a2, a3, b0, b1);
                mma16816(c[mt * 4 + 1], a0, a1, a2, a3, b2, b3);
                mma16816(c[mt * 4 + 2], a0, a1, a2, a3, b4, b5);
                mma16816(c[mt * 4 + 3], a0, a1, a2, a3, b6, b7);
            }
        }
        __syncthreads();
    }

#pragma unroll
    for (int nt = 0; nt < 4; nt++) {
#pragma unroll
        for (int q = 0; q < 2; q++) {
            float ps = 0.f, pd = 0.f;
#pragma unroll
            for (int mt = 0; mt < 4; mt++) {
                const float* cf = c[mt * 4 + nt];
                ps += cf[q] * as0[mt] + cf[q + 2] * as1[mt];
                pd += cf[q] * ad0[mt] + cf[q + 2] * ad1[mt];
            }
#pragma unroll
            for (int o = 4; o < 32; o <<= 1) {
                ps += __shfl_xor_sync(0xffffffffu, ps, o);
                pd += __shfl_xor_sync(0xffffffffu, pd, o);
            }
            if (lane < 4) {
                int j = nq * 32 + nt * 8 + 2 * lane + q;
                atomicAdd(&s_sm[j], ps);
                atomicAdd(&d_sm[j], pd);
            }
        }
    }

#pragma unroll
    for (int mt = 0; mt < 4; mt++) {
        int dlo = mh * 64 + mt * 16 + (lane >> 2);
        int jg  = jloc + nq * 32 + 2 * (lane & 3);
#pragma unroll
        for (int nt = 0; nt < 4; nt++) {
            const float* cf = c[mt * 4 + nt];
            __half2 lo = __floats2half2_rn(cf[0], cf[1]);
            __half2 hi = __floats2half2_rn(cf[2], cf[3]);
            *(uint32_t*)&g_hT[((size_t)(batch * OUT_DIM + dlo)) * N_ + jg + nt * 8]
                = *(uint32_t*)&lo;
            *(uint32_t*)&g_hT[((size_t)(batch * OUT_DIM + dlo + 8)) * N_ + jg + nt * 8]
                = *(uint32_t*)&hi;
        }
    }

    __syncthreads();
    if (tid < 128) {
        float s = s_sm[tid], d = d_sm[tid];
        g_S[j0g + tid] = make_float2(expf(s * 0.5f), expf(s * 0.1f));
        g_E[j0g + tid] = make_float2(expf(d * 0.5f), expf(d * 0.1f));
    }
}

// ---------------------------------------------------------------------------
// kAB: fused masked-softmax weights + mma.sync f16 aggregation.
// R10 config (RCTA=128, TJ=128, grid 128, 2-stage h, 2-buffer alpha) with
// the weight pass INTERLEAVED into the MMA ks loop: 2 weight rows (tile t+1)
// + 2 A-prefetch rows (tile t+2) per ks step -> tensor pipe stays fed while
// scalar work issues. Numerics identical to R10.
// ---------------------------------------------------------------------------
#define HT2_B   (OUT_DIM * PITCH2)          // 34816
#define AL2_B   (RCTA * PITCH2)             // 34816
#define AL2_OFF (2 * HT2_B)                 // 69632
#define AB_DSM  (AL2_OFF + 2 * AL2_B)       // 139264

__global__ void __launch_bounds__(256, 1) kAB(const float* __restrict__ A,
                                              float* __restrict__ out) {
    extern __shared__ __align__(16) char dsm[];
    __shared__ float s_z[RCTA];

    const int tid  = threadIdx.x;
    const int wid  = tid >> 5, lane = tid & 31;
    const int batch = blockIdx.x >> 5;
    const int row0  = (blockIdx.x & 31) << 7;
    const size_t rbase = (size_t)batch * N_;

    const uint32_t smb = sm_u32(dsm);
    const __half* hTb = g_hT + (size_t)batch * OUT_DIM * N_;

    float S1[16], S2[16], z[16];
#pragma unroll
    for (int r = 0; r < 16; r++) {
        float2 sv = g_S[rbase + row0 + wid * 16 + r];
        S1[r] = sv.x; S2[r] = sv.y; z[r] = 0.f;
    }
    const float* Abase = A + (rbase + row0 + wid * 16) * (size_t)N_ + 4 * lane;

    const int mh = wid & 1, nq = wid >> 1;
    const uint32_t aoff_l = (uint32_t)((mh * 64 + (lane & 15)) * PITCH2
                                       + ((lane >> 4) << 4));
    const uint32_t boff_l = (uint32_t)((nq * 32 + ((lane >> 4) << 3) + (lane & 7)) * PITCH2
                                       + (((lane >> 3) & 1) << 4));

    float c[16][4];
#pragma unroll
    for (int q = 0; q < 16; q++)
        c[q][0] = c[q][1] = c[q][2] = c[q][3] = 0.f;

    float4 AR[16];
    float4 EcA, EcB;   // E for the tile currently being weighted
    float4 EnA, EnB;   // E prefetch for the next weight tile

#define ISSUE_H(T, S)                                                         \
    do {                                                                      \
        const int jt_ = (T) * TJ2;                                            \
        uint32_t hd_ = smb + (S) * HT2_B;                                     \
        _Pragma("unroll")                                                     \
        for (int i = 0; i < 8; i++) {                                         \
            int f_ = tid + 256 * i;                                           \
            int dd_ = f_ >> 4, ch_ = f_ & 15;                                 \
            cp16(hd_ + dd_ * PITCH2 + ch_ * 16,                               \
                 hTb + (size_t)dd_ * N_ + jt_ + ch_ * 8);                     \
        }                                                                     \
        cp_commit();                                                          \
    } while (0)

#define LOAD_EV(T, EA, EB)                                                    \
    do {                                                                      \
        EA = *(const float4*)&g_E[rbase + (T) * TJ2 + 4 * lane];              \
        EB = *(const float4*)&g_E[rbase + (T) * TJ2 + 4 * lane + 2];          \
    } while (0)

#define AROW(R, T)                                                            \
    AR[R] = *(const float4*)(Abase + (size_t)(R) * N_ + (T) * TJ2)

#define WROW(R)                                                               \
    do {                                                                      \
        float4 av = AR[R];                                                    \
        float w0 = fmaxf(S1[R] * EcA.x, S2[R] * EcA.y);                       \
        float w1 = fmaxf(S1[R] * EcA.z, S2[R] * EcA.w);                       \
        float w2 = fmaxf(S1[R] * EcB.x, S2[R] * EcB.y);                       \
        float w3 = fmaxf(S1[R] * EcB.z, S2[R] * EcB.w);                       \
        w0 = av.x >= 1e-9f ? w0 : 0.f;                                        \
        w1 = av.y >= 1e-9f ? w1 : 0.f;                                        \
        w2 = av.z >= 1e-9f ? w2 : 0.f;                                        \
        w3 = av.w >= 1e-9f ? w3 : 0.f;                                        \
        z[R] += (w0 + w1) + (w2 + w3);                                        \
        __half2 p0 = __floats2half2_rn(w0, w1);                               \
        __half2 p1 = __floats2half2_rn(w2, w3);                               \
        uint2 u_; u_.x = *(uint32_t*)&p0; u_.y = *(uint32_t*)&p1;             \
        *(uint2*)&sal[(wid * 16 + (R)) * PAD2 + 4 * lane] = u_;               \
    } while (0)

    // prologue: weights(0) bulk; A(1)+E(1) loaded for interleaved weighting
    LOAD_EV(0, EcA, EcB);
#pragma unroll
    for (int r = 0; r < 16; r++) AROW(r, 0);
    ISSUE_H(0, 0);
    {
        __half* sal = (__half*)(dsm + AL2_OFF);   // buf 0
#pragma unroll
        for (int r = 0; r < 16; r++) WROW(r);
    }
    LOAD_EV(1, EcA, EcB);
#pragma unroll
    for (int r = 0; r < 16; r++) AROW(r, 1);

    for (int t = 0; t < NT2; t++) {
        cp_wait<0>();
        __syncthreads();   // h(t) staged, alpha(t) visible, WAR safe

        const bool doW = (t + 1 < NT2);
        const bool doL = (t + 2 < NT2);
        if (doW) ISSUE_H(t + 1, (t + 1) & 1);
        if (doL) LOAD_EV(t + 2, EnA, EnB);
        __half* sal = (__half*)(dsm + AL2_OFF + ((t + 1) & 1) * AL2_B);

        const uint32_t ab = smb + AL2_OFF + (t & 1) * AL2_B + aoff_l;
        const uint32_t hb = smb + (t & 1) * HT2_B + boff_l;
#pragma unroll
        for (int ks = 0; ks < 8; ks++) {
            uint32_t b0, b1, b2, b3, b4, b5, b6, b7;
            ldsm_x4(b0, b1, b2, b3, hb + ks * 32);
            ldsm_x4(b4, b5, b6, b7, hb + 16 * PITCH2 + ks * 32);
#pragma unroll
            for (int mt = 0; mt < 4; mt++) {
                uint32_t a0, a1, a2, a3;
                ldsm_x4(a0, a1, a2, a3, ab + mt * 16 * PITCH2 + ks * 32);
                mma16816(c[mt * 4 + 0], a0, a1, a2, a3, b0, b1);
                mma16816(c[mt * 4 + 1], a0, a1, a2, a3, b2, b3);
                mma16816(c[mt * 4 + 2], a0, a1, a2, a3, b4, b5);
                mma16816(c[mt * 4 + 3], a0, a1, a2, a3, b6, b7);
            }
            // interleaved scalar work: weights for tile t+1, A loads for t+2
            if (doW) { WROW(2 * ks); WROW(2 * ks + 1); }
            if (doL) { AROW(2 * ks, t + 2); AROW(2 * ks + 1, t + 2); }
        }
        EcA = EnA; EcB = EnB;
    }

    // z row sums
#pragma unroll
    for (int r = 0; r < 16; r++) {
        float zz = z[r];
#pragma unroll
        for (int o = 16; o; o >>= 1) zz += __shfl_xor_sync(0xffffffffu, zz, o);
        if (lane == 0) s_z[wid * 16 + r] = zz;
    }
    __syncthreads();

    // epilogue
#pragma unroll
    for (int mt = 0; mt < 4; mt++) {
        const int rlo = mh * 64 + mt * 16 + (lane >> 2);
        const float zlo = s_z[rlo], zhi = s_z[rlo + 8];
        const float invlo = zlo > 0.f ? 1.f / zlo : 0.f;
        const float invhi = zhi > 0.f ? 1.f / zhi : 0.f;
        float* olo = out + (rbase + row0 + rlo) * OUT_DIM + nq * 32 + 2 * (lane & 3);
        float* ohi = olo + 8 * OUT_DIM;
#pragma unroll
        for (int nt = 0; nt < 4; nt++) {
            const float* cf = c[mt * 4 + nt];
            *(float2*)(olo + nt * 8) = make_float2(cf[0] * invlo, cf[1] * invlo);
            *(float2*)(ohi + nt * 8) = make_float2(cf[2] * invhi, cf[3] * invhi);
        }
    }
}

// ---------------------------------------------------------------------------
extern "C" void kernel_launch(void* const* d_in, const int* in_sizes, int n_in,
                              void* d_out, int out_size) {
    const float* x     = (const float*)d_in[0];   // [4,4096,256]
    const float* A     = (const float*)d_in[1];   // [4,4096,4096]
    const float* W     = (const float*)d_in[2];   // [256,128]
    const float* a_src = (const float*)d_in[3];   // [128]
    const float* a_dst = (const float*)d_in[4];   // [128]
    float* out = (float*)d_out;                   // [4,4096,128]

    cudaFuncSetAttribute(k1_gemm, cudaFuncAttributeMaxDynamicSharedMemorySize,
                         K1_DSM);
    cudaFuncSetAttribute(kAB, cudaFuncAttributeMaxDynamicSharedMemorySize,
                         AB_DSM);

    k1_gemm<<<NROWS / 128, 256, K1_DSM>>>(x, W, a_src, a_dst);
    kAB    <<<NROWS / RCTA, 256, AB_DSM>>>(A, out);
    (void)in_sizes; (void)n_in; (void)out_size;
}

// round 13
// speedup vs baseline: 1.1022x; 1.1022x over previous
#include <cuda_runtime.h>
#include <cuda_fp16.h>
#include <math.h>
#include <stdint.h>

#define B_ 4
#define N_ 4096
#define IN_DIM 256
#define OUT_DIM 128
#define NROWS (B_ * N_)
#define PADH 72            // k1 smem half pitch (144B rows)
#define TJ2 128            // kAB j-tile
#define NT2 (N_ / TJ2)     // 32 tiles
#define PAD2 136           // kAB smem pitch in halves (272B)
#define PITCH2 272
#define RCTA 128

// Scratch (no cudaMalloc allowed)
__device__ __half g_hT[(size_t)B_ * OUT_DIM * N_];// f16 h^T: [b][d][j]
__device__ float2 g_S [NROWS];                    // (exp(s/2), exp(s/10))
__device__ float2 g_E [NROWS];                    // (exp(d/2), exp(d/10))

// ---------------------------------------------------------------------------
__device__ __forceinline__ uint32_t sm_u32(const void* p) {
    uint32_t a;
    asm("{ .reg .u64 t; cvta.to.shared.u64 t, %1; cvt.u32.u64 %0, t; }"
        : "=r"(a) : "l"(p));
    return a;
}
__device__ __forceinline__ void cp16(uint32_t dst, const void* src) {
    asm volatile("cp.async.cg.shared.global [%0], [%1], 16;"
                 :: "r"(dst), "l"(src));
}
__device__ __forceinline__ void cp_commit() {
    asm volatile("cp.async.commit_group;" ::: "memory");
}
template <int N>
__device__ __forceinline__ void cp_wait() {
    asm volatile("cp.async.wait_group %0;" :: "n"(N) : "memory");
}
__device__ __forceinline__ void ldsm_x4(uint32_t& r0, uint32_t& r1,
                                        uint32_t& r2, uint32_t& r3,
                                        uint32_t addr) {
    asm volatile("ldmatrix.sync.aligned.m8n8.x4.shared.b16 {%0,%1,%2,%3}, [%4];"
                 : "=r"(r0), "=r"(r1), "=r"(r2), "=r"(r3) : "r"(addr));
}
__device__ __forceinline__ void mma16816(float* c,
                                         uint32_t a0, uint32_t a1,
                                         uint32_t a2, uint32_t a3,
                                         uint32_t b0, uint32_t b1) {
    asm volatile("mma.sync.aligned.m16n8k16.row.col.f32.f16.f16.f32 "
                 "{%0,%1,%2,%3},{%4,%5,%6,%7},{%8,%9},{%0,%1,%2,%3};"
                 : "+f"(c[0]), "+f"(c[1]), "+f"(c[2]), "+f"(c[3])
                 : "r"(a0), "r"(a1), "r"(a2), "r"(a3), "r"(b0), "r"(b1));
}

// ---------------------------------------------------------------------------
// k1: hT = W^T x^T via mma.sync f16 (M=d=128, N=j=128/CTA, K=256).
// W transposed to f16 in-prologue. Fused s/d reductions -> g_S / g_E.
// (R12 version — passed; regression was kAB-only.)
// ---------------------------------------------------------------------------
#define WT_PITCH_B 528
#define WT_BYTES   (OUT_DIM * WT_PITCH_B)
#define XS_BYTES   (128 * PADH * 2)
#define K1_DSM     (WT_BYTES + 2 * XS_BYTES)

__global__ void __launch_bounds__(256) k1_gemm(const float* __restrict__ x,
                                               const float* __restrict__ W,
                                               const float* __restrict__ a_src,
                                               const float* __restrict__ a_dst) {
    extern __shared__ __align__(16) char dsm[];
    __shared__ float s_sm[128], d_sm[128];

    const int tid  = threadIdx.x;
    const int wid  = tid >> 5, lane = tid & 31;
    const int j0g  = blockIdx.x * 128;
    const int batch = j0g >> 12;
    const int jloc  = j0g & (N_ - 1);

    if (tid < 128) { s_sm[tid] = 0.f; d_sm[tid] = 0.f; }

    const uint32_t smb = sm_u32(dsm);

    float4 XR[8];
    const int xj = tid >> 4, xk = (tid & 15) << 2;

#define LDG_X(CH)                                                             \
    do {                                                                      \
        _Pragma("unroll")                                                     \
        for (int i = 0; i < 8; i++)                                           \
            XR[i] = *(const float4*)&x[(size_t)(j0g + xj + i * 16) * IN_DIM   \
                                       + (CH) * 64 + xk];                     \
    } while (0)

    LDG_X(0);   // overlap x loads with W transpose below

    // W[k][d] fp32 -> smem WT f16 [d][k] (pitch 528B), via fp32 smem scratch
    {
        float* sx = (float*)(dsm + WT_BYTES);   // 32 x 132 fp32 scratch
        for (int kc0 = 0; kc0 < IN_DIM; kc0 += 32) {
#pragma unroll
            for (int i = 0; i < 4; i++) {
                int f  = tid + 256 * i;
                int kk = f >> 5, d4 = (f & 31) << 2;
                float4 v = *(const float4*)&W[(size_t)(kc0 + kk) * OUT_DIM + d4];
                sx[kk * 132 + d4 + 0] = v.x; sx[kk * 132 + d4 + 1] = v.y;
                sx[kk * 132 + d4 + 2] = v.z; sx[kk * 132 + d4 + 3] = v.w;
            }
            __syncthreads();
            {
                int d = tid >> 1, kh = (tid & 1) << 4;
#pragma unroll
                for (int q = 0; q < 8; q++) {
                    __half2 h = __floats2half2_rn(sx[(kh + 2 * q) * 132 + d],
                                                  sx[(kh + 2 * q + 1) * 132 + d]);
                    *(__half2*)(dsm + d * WT_PITCH_B + (kc0 + kh + 2 * q) * 2) = h;
                }
            }
            __syncthreads();
        }
    }

    const int mh = wid & 1, nq = wid >> 1;
    const uint32_t aoff = (uint32_t)((mh * 64 + (lane & 15)) * WT_PITCH_B
                                     + ((lane >> 4) << 4));
    const uint32_t boff = (uint32_t)((nq * 32 + ((lane >> 4) << 3) + (lane & 7)) * (PADH * 2)
                                     + (((lane >> 3) & 1) << 4));

    float as0[4], as1[4], ad0[4], ad1[4];
#pragma unroll
    for (int mt = 0; mt < 4; mt++) {
        int d0 = mh * 64 + mt * 16 + (lane >> 2);
        as0[mt] = a_src[d0]; as1[mt] = a_src[d0 + 8];
        ad0[mt] = a_dst[d0]; ad1[mt] = a_dst[d0 + 8];
    }

    float c[16][4];
#pragma unroll
    for (int q = 0; q < 16; q++)
        c[q][0] = c[q][1] = c[q][2] = c[q][3] = 0.f;

    for (int ch = 0; ch < 4; ch++) {
        {
            char* xb = dsm + WT_BYTES + (ch & 1) * XS_BYTES;
#pragma unroll
            for (int i = 0; i < 8; i++) {
                __half2 p0 = __floats2half2_rn(XR[i].x, XR[i].y);
                __half2 p1 = __floats2half2_rn(XR[i].z, XR[i].w);
                uint2 u; u.x = *(uint32_t*)&p0; u.y = *(uint32_t*)&p1;
                *(uint2*)(xb + (xj + i * 16) * (PADH * 2) + xk * 2) = u;
            }
        }
        __syncthreads();
        if (ch < 3) LDG_X(ch + 1);

        const uint32_t ab = smb + aoff + ch * 128;
        const uint32_t bb = smb + WT_BYTES + (ch & 1) * XS_BYTES + boff;
#pragma unroll
        for (int ks = 0; ks < 4; ks++) {
            uint32_t b0, b1, b2, b3, b4, b5, b6, b7;
            ldsm_x4(b0, b1, b2, b3, bb + ks * 32);
            ldsm_x4(b4, b5, b6, b7, bb + 16 * (PADH * 2) + ks * 32);
#pragma unroll
            for (int mt = 0; mt < 4; mt++) {
                uint32_t a0, a1, a2, a3;
                ldsm_x4(a0, a1, a2, a3, ab + mt * 16 * WT_PITCH_B + ks * 32);
                mma16816(c[mt * 4 + 0], a0, a1, a2, a3, b0, b1);
                mma16816(c[mt * 4 + 1], a0, a1, a2, a3, b2, b3);
                mma16816(c[mt * 4 + 2], a0, a1, a2, a3, b4, b5);
                mma16816(c[mt * 4 + 3], a0, a1, a2, a3, b6, b7);
            }
        }
        __syncthreads();
    }

#pragma unroll
    for (int nt = 0; nt < 4; nt++) {
#pragma unroll
        for (int q = 0; q < 2; q++) {
            float ps = 0.f, pd = 0.f;
#pragma unroll
            for (int mt = 0; mt < 4; mt++) {
                const float* cf = c[mt * 4 + nt];
                ps += cf[q] * as0[mt] + cf[q + 2] * as1[mt];
                pd += cf[q] * ad0[mt] + cf[q + 2] * ad1[mt];
            }
#pragma unroll
            for (int o = 4; o < 32; o <<= 1) {
                ps += __shfl_xor_sync(0xffffffffu, ps, o);
                pd += __shfl_xor_sync(0xffffffffu, pd, o);
            }
            if (lane < 4) {
                int j = nq * 32 + nt * 8 + 2 * lane + q;
                atomicAdd(&s_sm[j], ps);
                atomicAdd(&d_sm[j], pd);
            }
        }
    }

#pragma unroll
    for (int mt = 0; mt < 4; mt++) {
        int dlo = mh * 64 + mt * 16 + (lane >> 2);
        int jg  = jloc + nq * 32 + 2 * (lane & 3);
#pragma unroll
        for (int nt = 0; nt < 4; nt++) {
            const float* cf = c[mt * 4 + nt];
            __half2 lo = __floats2half2_rn(cf[0], cf[1]);
            __half2 hi = __floats2half2_rn(cf[2], cf[3]);
            *(uint32_t*)&g_hT[((size_t)(batch * OUT_DIM + dlo)) * N_ + jg + nt * 8]
                = *(uint32_t*)&lo;
            *(uint32_t*)&g_hT[((size_t)(batch * OUT_DIM + dlo + 8)) * N_ + jg + nt * 8]
                = *(uint32_t*)&hi;
        }
    }

    __syncthreads();
    if (tid < 128) {
        float s = s_sm[tid], d = d_sm[tid];
        g_S[j0g + tid] = make_float2(expf(s * 0.5f), expf(s * 0.1f));
        g_E[j0g + tid] = make_float2(expf(d * 0.5f), expf(d * 0.1f));
    }
}

// ---------------------------------------------------------------------------
// kAB: fused masked-softmax weights + mma.sync f16 aggregation.
// 512 threads (16 warps) per CTA, RCTA=128, TJ=128, grid 128 — doubles
// latency hiding vs R10 with identical DRAM/cp.async traffic. MMA split
// ms=4 x ns=4 (warp: 32 rows x 32 dims). Weight pass: 8 rows/warp.
// R10 numerics (fp32 weights, fp32 z in regs).
// ---------------------------------------------------------------------------
#define NTHR 512
#define HT2_B   (OUT_DIM * PITCH2)          // 34816
#define AL2_B   (RCTA * PITCH2)             // 34816
#define AL2_OFF (2 * HT2_B)                 // 69632
#define AB_DSM  (AL2_OFF + 2 * AL2_B)       // 139264

__global__ void __launch_bounds__(NTHR, 1) kAB(const float* __restrict__ A,
                                               float* __restrict__ out) {
    extern __shared__ __align__(16) char dsm[];
    __shared__ float s_z[RCTA];

    const int tid  = threadIdx.x;
    const int wid  = tid >> 5, lane = tid & 31;
    const int batch = blockIdx.x >> 5;
    const int row0  = (blockIdx.x & 31) << 7;
    const size_t rbase = (size_t)batch * N_;

    const uint32_t smb = sm_u32(dsm);
    const __half* hTb = g_hT + (size_t)batch * OUT_DIM * N_;

    // weight pass: warp covers rows wid*8..+7; lane covers cols 4l..4l+3
    float S1[8], S2[8], z[8];
#pragma unroll
    for (int r = 0; r < 8; r++) {
        float2 sv = g_S[rbase + row0 + wid * 8 + r];
        S1[r] = sv.x; S2[r] = sv.y; z[r] = 0.f;
    }
    const float* Abase = A + (rbase + row0 + wid * 8) * (size_t)N_ + 4 * lane;

    // MMA split: mh = wid&3 (32 rows), nq = wid>>2 (32 d)
    const int mh = wid & 3, nq = wid >> 2;
    const uint32_t aoff_l = (uint32_t)((mh * 32 + (lane & 15)) * PITCH2
                                       + ((lane >> 4) << 4));
    const uint32_t boff_l = (uint32_t)((nq * 32 + ((lane >> 4) << 3) + (lane & 7)) * PITCH2
                                       + (((lane >> 3) & 1) << 4));

    float c[8][4];
#pragma unroll
    for (int q = 0; q < 8; q++)
        c[q][0] = c[q][1] = c[q][2] = c[q][3] = 0.f;

    float4 AR[8];
    float4 EvA, EvB;

#define ISSUE_H(T, S)                                                         \
    do {                                                                      \
        const int jt_ = (T) * TJ2;                                            \
        uint32_t hd_ = smb + (S) * HT2_B;                                     \
        _Pragma("unroll")                                                     \
        for (int i = 0; i < 4; i++) {                                         \
            int f_ = tid + NTHR * i;                                          \
            int dd_ = f_ >> 4, ch_ = f_ & 15;                                 \
            cp16(hd_ + dd_ * PITCH2 + ch_ * 16,                               \
                 hTb + (size_t)dd_ * N_ + jt_ + ch_ * 8);                     \
        }                                                                     \
        cp_commit();                                                          \
    } while (0)

#define LOAD_A(T)                                                             \
    do {                                                                      \
        EvA = *(const float4*)&g_E[rbase + (T) * TJ2 + 4 * lane];             \
        EvB = *(const float4*)&g_E[rbase + (T) * TJ2 + 4 * lane + 2];         \
        _Pragma("unroll")                                                     \
        for (int r = 0; r < 8; r++)                                           \
            AR[r] = *(const float4*)(Abase + (size_t)r * N_ + (T) * TJ2);     \
    } while (0)

#define WEIGHT(T)                                                             \
    do {                                                                      \
        __half* sal = (__half*)(dsm + AL2_OFF + ((T) & 1) * AL2_B);           \
        _Pragma("unroll")                                                     \
        for (int r = 0; r < 8; r++) {                                         \
            float4 av = AR[r];                                                \
            float w0 = fmaxf(S1[r] * EvA.x, S2[r] * EvA.y);                   \
            float w1 = fmaxf(S1[r] * EvA.z, S2[r] * EvA.w);                   \
            float w2 = fmaxf(S1[r] * EvB.x, S2[r] * EvB.y);                   \
            float w3 = fmaxf(S1[r] * EvB.z, S2[r] * EvB.w);                   \
            w0 = av.x >= 1e-9f ? w0 : 0.f;                                    \
            w1 = av.y >= 1e-9f ? w1 : 0.f;                                    \
            w2 = av.z >= 1e-9f ? w2 : 0.f;                                    \
            w3 = av.w >= 1e-9f ? w3 : 0.f;                                    \
            z[r] += (w0 + w1) + (w2 + w3);                                    \
            __half2 p0 = __floats2half2_rn(w0, w1);                           \
            __half2 p1 = __floats2half2_rn(w2, w3);                           \
            uint2 u_; u_.x = *(uint32_t*)&p0; u_.y = *(uint32_t*)&p1;         \
            *(uint2*)&sal[(wid * 8 + r) * PAD2 + 4 * lane] = u_;              \
        }                                                                     \
    } while (0)

    // prologue
    LOAD_A(0);
    ISSUE_H(0, 0);
    WEIGHT(0);
    LOAD_A(1);

    for (int t = 0; t < NT2; t++) {
        cp_wait<0>();
        __syncthreads();   // h(t) staged, alpha(t) visible, WAR safe

        if (t + 1 < NT2) {
            ISSUE_H(t + 1, (t + 1) & 1);
            WEIGHT(t + 1);
            if (t + 2 < NT2) LOAD_A(t + 2);
        }

        const uint32_t ab = smb + AL2_OFF + (t & 1) * AL2_B + aoff_l;
        const uint32_t hb = smb + (t & 1) * HT2_B + boff_l;
#pragma unroll
        for (int ks = 0; ks < 8; ks++) {
            uint32_t b0, b1, b2, b3, b4, b5, b6, b7;
            ldsm_x4(b0, b1, b2, b3, hb + ks * 32);
            ldsm_x4(b4, b5, b6, b7, hb + 16 * PITCH2 + ks * 32);
#pragma unroll
            for (int mt = 0; mt < 2; mt++) {
                uint32_t a0, a1, a2, a3;
                ldsm_x4(a0, a1, a2, a3, ab + mt * 16 * PITCH2 + ks * 32);
                mma16816(c[mt * 4 + 0], a0, a1, a2, a3, b0, b1);
                mma16816(c[mt * 4 + 1], a0, a1, a2, a3, b2, b3);
                mma16816(c[mt * 4 + 2], a0, a1, a2, a3, b4, b5);
                mma16816(c[mt * 4 + 3], a0, a1, a2, a3, b6, b7);
            }
        }
    }

    // z row sums (each warp owns rows wid*8..+7)
#pragma unroll
    for (int r = 0; r < 8; r++) {
        float zz = z[r];
#pragma unroll
        for (int o = 16; o; o >>= 1) zz += __shfl_xor_sync(0xffffffffu, zz, o);
        if (lane == 0) s_z[wid * 8 + r] = zz;
    }
    __syncthreads();

    // epilogue: warp (mh, nq) covers rows mh*32..+31, cols nq*32..+31
#pragma unroll
    for (int mt = 0; mt < 2; mt++) {
        const int rlo = mh * 32 + mt * 16 + (lane >> 2);
        const float zlo = s_z[rlo], zhi = s_z[rlo + 8];
        const float invlo = zlo > 0.f ? 1.f / zlo : 0.f;
        const float invhi = zhi > 0.f ? 1.f / zhi : 0.f;
        float* olo = out + (rbase + row0 + rlo) * OUT_DIM + nq * 32 + 2 * (lane & 3);
        float* ohi = olo + 8 * OUT_DIM;
#pragma unroll
        for (int nt = 0; nt < 4; nt++) {
            const float* cf = c[mt * 4 + nt];
            *(float2*)(olo + nt * 8) = make_float2(cf[0] * invlo, cf[1] * invlo);
            *(float2*)(ohi + nt * 8) = make_float2(cf[2] * invhi, cf[3] * invhi);
        }
    }
}

// ---------------------------------------------------------------------------
extern "C" void kernel_launch(void* const* d_in, const int* in_sizes, int n_in,
                              void* d_out, int out_size) {
    const float* x     = (const float*)d_in[0];   // [4,4096,256]
    const float* A     = (const float*)d_in[1];   // [4,4096,4096]
    const float* W     = (const float*)d_in[2];   // [256,128]
    const float* a_src = (const float*)d_in[3];   // [128]
    const float* a_dst = (const float*)d_in[4];   // [128]
    float* out = (float*)d_out;                   // [4,4096,128]

    cudaFuncSetAttribute(k1_gemm, cudaFuncAttributeMaxDynamicSharedMemorySize,
                         K1_DSM);
    cudaFuncSetAttribute(kAB, cudaFuncAttributeMaxDynamicSharedMemorySize,
                         AB_DSM);

    k1_gemm<<<NROWS / 128, 256, K1_DSM>>>(x, W, a_src, a_dst);
    kAB    <<<NROWS / RCTA, NTHR, AB_DSM>>>(A, out);
    (void)in_sizes; (void)n_in; (void)out_size;
}

// round 14
// speedup vs baseline: 1.1887x; 1.0784x over previous
#include <cuda_runtime.h>
#include <cuda_fp16.h>
#include <math.h>
#include <stdint.h>

#define B_ 4
#define N_ 4096
#define IN_DIM 256
#define OUT_DIM 128
#define NROWS (B_ * N_)
#define PADH 72            // k1 smem half pitch (144B rows)
#define TJ2 128            // kAB j-tile
#define NT2 (N_ / TJ2)     // 32 tiles
#define PAD2 136           // kAB smem pitch in halves (272B)
#define PITCH2 272
#define RCTA 128

// Scratch (no cudaMalloc allowed)
__device__ __half g_hT[(size_t)B_ * OUT_DIM * N_];// f16 h^T: [b][d][j]
__device__ float2 g_S [NROWS];                    // (exp(s/2), exp(s/10))
__device__ float2 g_E [NROWS];                    // (exp(d/2), exp(d/10))

// ---------------------------------------------------------------------------
__device__ __forceinline__ uint32_t sm_u32(const void* p) {
    uint32_t a;
    asm("{ .reg .u64 t; cvta.to.shared.u64 t, %1; cvt.u32.u64 %0, t; }"
        : "=r"(a) : "l"(p));
    return a;
}
__device__ __forceinline__ void cp16(uint32_t dst, const void* src) {
    asm volatile("cp.async.cg.shared.global [%0], [%1], 16;"
                 :: "r"(dst), "l"(src));
}
__device__ __forceinline__ void cp_commit() {
    asm volatile("cp.async.commit_group;" ::: "memory");
}
template <int N>
__device__ __forceinline__ void cp_wait() {
    asm volatile("cp.async.wait_group %0;" :: "n"(N) : "memory");
}
__device__ __forceinline__ void ldsm_x4(uint32_t& r0, uint32_t& r1,
                                        uint32_t& r2, uint32_t& r3,
                                        uint32_t addr) {
    asm volatile("ldmatrix.sync.aligned.m8n8.x4.shared.b16 {%0,%1,%2,%3}, [%4];"
                 : "=r"(r0), "=r"(r1), "=r"(r2), "=r"(r3) : "r"(addr));
}
__device__ __forceinline__ void mma16816(float* c,
                                         uint32_t a0, uint32_t a1,
                                         uint32_t a2, uint32_t a3,
                                         uint32_t b0, uint32_t b1) {
    asm volatile("mma.sync.aligned.m16n8k16.row.col.f32.f16.f16.f32 "
                 "{%0,%1,%2,%3},{%4,%5,%6,%7},{%8,%9},{%0,%1,%2,%3};"
                 : "+f"(c[0]), "+f"(c[1]), "+f"(c[2]), "+f"(c[3])
                 : "r"(a0), "r"(a1), "r"(a2), "r"(a3), "r"(b0), "r"(b1));
}

// ---------------------------------------------------------------------------
// k1: hT = W^T x^T via mma.sync f16 (M=d=128, N=j=128/CTA, K=256).
// W transposed to f16 in-prologue (kW folded in). Fused s/d reductions ->
// g_S / g_E exp tables. (R12/R13 version — measured 14.6us.)
// ---------------------------------------------------------------------------
#define WT_PITCH_B 528
#define WT_BYTES   (OUT_DIM * WT_PITCH_B)
#define XS_BYTES   (128 * PADH * 2)
#define K1_DSM     (WT_BYTES + 2 * XS_BYTES)

__global__ void __launch_bounds__(256) k1_gemm(const float* __restrict__ x,
                                               const float* __restrict__ W,
                                               const float* __restrict__ a_src,
                                               const float* __restrict__ a_dst) {
    extern __shared__ __align__(16) char dsm[];
    __shared__ float s_sm[128], d_sm[128];

    const int tid  = threadIdx.x;
    const int wid  = tid >> 5, lane = tid & 31;
    const int j0g  = blockIdx.x * 128;
    const int batch = j0g >> 12;
    const int jloc  = j0g & (N_ - 1);

    if (tid < 128) { s_sm[tid] = 0.f; d_sm[tid] = 0.f; }

    const uint32_t smb = sm_u32(dsm);

    float4 XR[8];
    const int xj = tid >> 4, xk = (tid & 15) << 2;

#define LDG_X(CH)                                                             \
    do {                                                                      \
        _Pragma("unroll")                                                     \
        for (int i = 0; i < 8; i++)                                           \
            XR[i] = *(const float4*)&x[(size_t)(j0g + xj + i * 16) * IN_DIM   \
                                       + (CH) * 64 + xk];                     \
    } while (0)

    LDG_X(0);   // overlap x loads with W transpose below

    // W[k][d] fp32 -> smem WT f16 [d][k] (pitch 528B), via fp32 smem scratch
    {
        float* sx = (float*)(dsm + WT_BYTES);   // 32 x 132 fp32 scratch
        for (int kc0 = 0; kc0 < IN_DIM; kc0 += 32) {
#pragma unroll
            for (int i = 0; i < 4; i++) {
                int f  = tid + 256 * i;
                int kk = f >> 5, d4 = (f & 31) << 2;
                float4 v = *(const float4*)&W[(size_t)(kc0 + kk) * OUT_DIM + d4];
                sx[kk * 132 + d4 + 0] = v.x; sx[kk * 132 + d4 + 1] = v.y;
                sx[kk * 132 + d4 + 2] = v.z; sx[kk * 132 + d4 + 3] = v.w;
            }
            __syncthreads();
            {
                int d = tid >> 1, kh = (tid & 1) << 4;
#pragma unroll
                for (int q = 0; q < 8; q++) {
                    __half2 h = __floats2half2_rn(sx[(kh + 2 * q) * 132 + d],
                                                  sx[(kh + 2 * q + 1) * 132 + d]);
                    *(__half2*)(dsm + d * WT_PITCH_B + (kc0 + kh + 2 * q) * 2) = h;
                }
            }
            __syncthreads();
        }
    }

    const int mh = wid & 1, nq = wid >> 1;
    const uint32_t aoff = (uint32_t)((mh * 64 + (lane & 15)) * WT_PITCH_B
                                     + ((lane >> 4) << 4));
    const uint32_t boff = (uint32_t)((nq * 32 + ((lane >> 4) << 3) + (lane & 7)) * (PADH * 2)
                                     + (((lane >> 3) & 1) << 4));

    float as0[4], as1[4], ad0[4], ad1[4];
#pragma unroll
    for (int mt = 0; mt < 4; mt++) {
        int d0 = mh * 64 + mt * 16 + (lane >> 2);
        as0[mt] = a_src[d0]; as1[mt] = a_src[d0 + 8];
        ad0[mt] = a_dst[d0]; ad1[mt] = a_dst[d0 + 8];
    }

    float c[16][4];
#pragma unroll
    for (int q = 0; q < 16; q++)
        c[q][0] = c[q][1] = c[q][2] = c[q][3] = 0.f;

    for (int ch = 0; ch < 4; ch++) {
        {
            char* xb = dsm + WT_BYTES + (ch & 1) * XS_BYTES;
#pragma unroll
            for (int i = 0; i < 8; i++) {
                __half2 p0 = __floats2half2_rn(XR[i].x, XR[i].y);
                __half2 p1 = __floats2half2_rn(XR[i].z, XR[i].w);
                uint2 u; u.x = *(uint32_t*)&p0; u.y = *(uint32_t*)&p1;
                *(uint2*)(xb + (xj + i * 16) * (PADH * 2) + xk * 2) = u;
            }
        }
        __syncthreads();
        if (ch < 3) LDG_X(ch + 1);

        const uint32_t ab = smb + aoff + ch * 128;
        const uint32_t bb = smb + WT_BYTES + (ch & 1) * XS_BYTES + boff;
#pragma unroll
        for (int ks = 0; ks < 4; ks++) {
            uint32_t b0, b1, b2, b3, b4, b5, b6, b7;
            ldsm_x4(b0, b1, b2, b3, bb + ks * 32);
            ldsm_x4(b4, b5, b6, b7, bb + 16 * (PADH * 2) + ks * 32);
#pragma unroll
            for (int mt = 0; mt < 4; mt++) {
                uint32_t a0, a1, a2, a3;
                ldsm_x4(a0, a1, a2, a3, ab + mt * 16 * WT_PITCH_B + ks * 32);
                mma16816(c[mt * 4 + 0], a0, a1, a2, a3, b0, b1);
                mma16816(c[mt * 4 + 1], a0, a1, a2, a3, b2, b3);
                mma16816(c[mt * 4 + 2], a0, a1, a2, a3, b4, b5);
                mma16816(c[mt * 4 + 3], a0, a1, a2, a3, b6, b7);
            }
        }
        __syncthreads();
    }

#pragma unroll
    for (int nt = 0; nt < 4; nt++) {
#pragma unroll
        for (int q = 0; q < 2; q++) {
            float ps = 0.f, pd = 0.f;
#pragma unroll
            for (int mt = 0; mt < 4; mt++) {
                const float* cf = c[mt * 4 + nt];
                ps += cf[q] * as0[mt] + cf[q + 2] * as1[mt];
                pd += cf[q] * ad0[mt] + cf[q + 2] * ad1[mt];
            }
#pragma unroll
            for (int o = 4; o < 32; o <<= 1) {
                ps += __shfl_xor_sync(0xffffffffu, ps, o);
                pd += __shfl_xor_sync(0xffffffffu, pd, o);
            }
            if (lane < 4) {
                int j = nq * 32 + nt * 8 + 2 * lane + q;
                atomicAdd(&s_sm[j], ps);
                atomicAdd(&d_sm[j], pd);
            }
        }
    }

#pragma unroll
    for (int mt = 0; mt < 4; mt++) {
        int dlo = mh * 64 + mt * 16 + (lane >> 2);
        int jg  = jloc + nq * 32 + 2 * (lane & 3);
#pragma unroll
        for (int nt = 0; nt < 4; nt++) {
            const float* cf = c[mt * 4 + nt];
            __half2 lo = __floats2half2_rn(cf[0], cf[1]);
            __half2 hi = __floats2half2_rn(cf[2], cf[3]);
            *(uint32_t*)&g_hT[((size_t)(batch * OUT_DIM + dlo)) * N_ + jg + nt * 8]
                = *(uint32_t*)&lo;
            *(uint32_t*)&g_hT[((size_t)(batch * OUT_DIM + dlo + 8)) * N_ + jg + nt * 8]
                = *(uint32_t*)&hi;
        }
    }

    __syncthreads();
    if (tid < 128) {
        float s = s_sm[tid], d = d_sm[tid];
        g_S[j0g + tid] = make_float2(expf(s * 0.5f), expf(s * 0.1f));
        g_E[j0g + tid] = make_float2(expf(d * 0.5f), expf(d * 0.1f));
    }
}

// ---------------------------------------------------------------------------
// kAB: fused masked-softmax weights + mma.sync f16 aggregation.
// R10 VERBATIM: RCTA=128, TJ=128, grid 128, 256 thr, 2-stage cp.async h,
// 2-buffer alpha, 1 sync/tile. ~94% of legacy tensor roofline (82us).
// ---------------------------------------------------------------------------
#define HT2_B   (OUT_DIM * PITCH2)          // 34816
#define AL2_B   (RCTA * PITCH2)             // 34816
#define AL2_OFF (2 * HT2_B)                 // 69632
#define AB_DSM  (AL2_OFF + 2 * AL2_B)       // 139264

__global__ void __launch_bounds__(256, 1) kAB(const float* __restrict__ A,
                                              float* __restrict__ out) {
    extern __shared__ __align__(16) char dsm[];
    __shared__ float s_z[RCTA];

    const int tid  = threadIdx.x;
    const int wid  = tid >> 5, lane = tid & 31;
    const int batch = blockIdx.x >> 5;
    const int row0  = (blockIdx.x & 31) << 7;
    const size_t rbase = (size_t)batch * N_;

    const uint32_t smb = sm_u32(dsm);
    const __half* hTb = g_hT + (size_t)batch * OUT_DIM * N_;

    // weight pass: warp covers rows wid*16..+15; lane covers cols 4l..4l+3
    float S1[16], S2[16], z[16];
#pragma unroll
    for (int r = 0; r < 16; r++) {
        float2 sv = g_S[rbase + row0 + wid * 16 + r];
        S1[r] = sv.x; S2[r] = sv.y; z[r] = 0.f;
    }
    const float* Abase = A + (rbase + row0 + wid * 16) * (size_t)N_ + 4 * lane;

    // MMA split: mh = wid&1 (64 rows), nq = wid>>1 (32 d)
    const int mh = wid & 1, nq = wid >> 1;
    const uint32_t aoff_l = (uint32_t)((mh * 64 + (lane & 15)) * PITCH2
                                       + ((lane >> 4) << 4));
    const uint32_t boff_l = (uint32_t)((nq * 32 + ((lane >> 4) << 3) + (lane & 7)) * PITCH2
                                       + (((lane >> 3) & 1) << 4));

    float c[16][4];
#pragma unroll
    for (int q = 0; q < 16; q++)
        c[q][0] = c[q][1] = c[q][2] = c[q][3] = 0.f;

    float4 AR[16];
    float4 EvA, EvB;

#define ISSUE_H(T, S)                                                         \
    do {                                                                      \
        const int jt_ = (T) * TJ2;                                            \
        uint32_t hd_ = smb + (S) * HT2_B;                                     \
        _Pragma("unroll")                                                     \
        for (int i = 0; i < 8; i++) {                                         \
            int f_ = tid + 256 * i;                                           \
            int dd_ = f_ >> 4, ch_ = f_ & 15;                                 \
            cp16(hd_ + dd_ * PITCH2 + ch_ * 16,                               \
                 hTb + (size_t)dd_ * N_ + jt_ + ch_ * 8);                     \
        }                                                                     \
        cp_commit();                                                          \
    } while (0)

#define LOAD_A(T)                                                             \
    do {                                                                      \
        EvA = *(const float4*)&g_E[rbase + (T) * TJ2 + 4 * lane];             \
        EvB = *(const float4*)&g_E[rbase + (T) * TJ2 + 4 * lane + 2];         \
        _Pragma("unroll")                                                     \
        for (int r = 0; r < 16; r++)                                          \
            AR[r] = *(const float4*)(Abase + (size_t)r * N_ + (T) * TJ2);     \
    } while (0)

#define WEIGHT(T)                                                             \
    do {                                                                      \
        __half* sal = (__half*)(dsm + AL2_OFF + ((T) & 1) * AL2_B);           \
        _Pragma("unroll")                                                     \
        for (int r = 0; r < 16; r++) {                                        \
            float4 av = AR[r];                                                \
            float w0 = fmaxf(S1[r] * EvA.x, S2[r] * EvA.y);                   \
            float w1 = fmaxf(S1[r] * EvA.z, S2[r] * EvA.w);                   \
            float w2 = fmaxf(S1[r] * EvB.x, S2[r] * EvB.y);                   \
            float w3 = fmaxf(S1[r] * EvB.z, S2[r] * EvB.w);                   \
            w0 = av.x >= 1e-9f ? w0 : 0.f;                                    \
            w1 = av.y >= 1e-9f ? w1 : 0.f;                                    \
            w2 = av.z >= 1e-9f ? w2 : 0.f;                                    \
            w3 = av.w >= 1e-9f ? w3 : 0.f;                                    \
            z[r] += (w0 + w1) + (w2 + w3);                                    \
            __half2 p0 = __floats2half2_rn(w0, w1);                           \
            __half2 p1 = __floats2half2_rn(w2, w3);                           \
            uint2 u_; u_.x = *(uint32_t*)&p0; u_.y = *(uint32_t*)&p1;         \
            *(uint2*)&sal[(wid * 16 + r) * PAD2 + 4 * lane] = u_;             \
        }                                                                     \
    } while (0)

    // prologue
    LOAD_A(0);
    ISSUE_H(0, 0);
    WEIGHT(0);
    LOAD_A(1);

    for (int t = 0; t < NT2; t++) {
        cp_wait<0>();
        __syncthreads();   // h(t) staged, alpha(t) visible, WAR safe

        if (t + 1 < NT2) {
            ISSUE_H(t + 1, (t + 1) & 1);
            WEIGHT(t + 1);
            if (t + 2 < NT2) LOAD_A(t + 2);
        }

        const uint32_t ab = smb + AL2_OFF + (t & 1) * AL2_B + aoff_l;
        const uint32_t hb = smb + (t & 1) * HT2_B + boff_l;
#pragma unroll
        for (int ks = 0; ks < 8; ks++) {
            uint32_t b0, b1, b2, b3, b4, b5, b6, b7;
            ldsm_x4(b0, b1, b2, b3, hb + ks * 32);
            ldsm_x4(b4, b5, b6, b7, hb + 16 * PITCH2 + ks * 32);
#pragma unroll
            for (int mt = 0; mt < 4; mt++) {
                uint32_t a0, a1, a2, a3;
                ldsm_x4(a0, a1, a2, a3, ab + mt * 16 * PITCH2 + ks * 32);
                mma16816(c[mt * 4 + 0], a0, a1, a2, a3, b0, b1);
                mma16816(c[mt * 4 + 1], a0, a1, a2, a3, b2, b3);
                mma16816(c[mt * 4 + 2], a0, a1, a2, a3, b4, b5);
                mma16816(c[mt * 4 + 3], a0, a1, a2, a3, b6, b7);
            }
        }
    }

    // z row sums
#pragma unroll
    for (int r = 0; r < 16; r++) {
        float zz = z[r];
#pragma unroll
        for (int o = 16; o; o >>= 1) zz += __shfl_xor_sync(0xffffffffu, zz, o);
        if (lane == 0) s_z[wid * 16 + r] = zz;
    }
    __syncthreads();

    // epilogue
#pragma unroll
    for (int mt = 0; mt < 4; mt++) {
        const int rlo = mh * 64 + mt * 16 + (lane >> 2);
        const float zlo = s_z[rlo], zhi = s_z[rlo + 8];
        const float invlo = zlo > 0.f ? 1.f / zlo : 0.f;
        const float invhi = zhi > 0.f ? 1.f / zhi : 0.f;
        float* olo = out + (rbase + row0 + rlo) * OUT_DIM + nq * 32 + 2 * (lane & 3);
        float* ohi = olo + 8 * OUT_DIM;
#pragma unroll
        for (int nt = 0; nt < 4; nt++) {
            const float* cf = c[mt * 4 + nt];
            *(float2*)(olo + nt * 8) = make_float2(cf[0] * invlo, cf[1] * invlo);
            *(float2*)(ohi + nt * 8) = make_float2(cf[2] * invhi, cf[3] * invhi);
        }
    }
}

// ---------------------------------------------------------------------------
extern "C" void kernel_launch(void* const* d_in, const int* in_sizes, int n_in,
                              void* d_out, int out_size) {
    const float* x     = (const float*)d_in[0];   // [4,4096,256]
    const float* A     = (const float*)d_in[1];   // [4,4096,4096]
    const float* W     = (const float*)d_in[2];   // [256,128]
    const float* a_src = (const float*)d_in[3];   // [128]
    const float* a_dst = (const float*)d_in[4];   // [128]
    float* out = (float*)d_out;                   // [4,4096,128]

    cudaFuncSetAttribute(k1_gemm, cudaFuncAttributeMaxDynamicSharedMemorySize,
                         K1_DSM);
    cudaFuncSetAttribute(kAB, cudaFuncAttributeMaxDynamicSharedMemorySize,
                         AB_DSM);

    k1_gemm<<<NROWS / 128, 256, K1_DSM>>>(x, W, a_src, a_dst);
    kAB    <<<NROWS / RCTA, 256, AB_DSM>>>(A, out);
    (void)in_sizes; (void)n_in; (void)out_size;
}

// round 16
// speedup vs baseline: 1.2491x; 1.0509x over previous
#include <cuda_runtime.h>
#include <cuda_fp16.h>
#include <math.h>
#include <stdint.h>

#define B_ 4
#define N_ 4096
#define IN_DIM 256
#define OUT_DIM 128
#define NROWS (B_ * N_)
#define PADH 72            // k1 smem half pitch (144B rows)
#define TJ2 128            // kAB j-tile
#define NT2 (N_ / TJ2)     // 32 tiles
#define PAD2 136           // kAB smem pitch in halves (272B)
#define PITCH2 272
#define CPB 37             // kAB CTAs per batch (34x7 + 3x6 m16-tiles)
#define MAXMT 7
#define MAXROWS (MAXMT * 16)   // 112
#define MAXWR (MAXMT * 2)      // 14 weight rows per warp

// Scratch (no cudaMalloc allowed)
__device__ __half g_WT[OUT_DIM * IN_DIM];         // W^T f16: [d][k]
__device__ __half g_hT[(size_t)B_ * OUT_DIM * N_];// f16 h^T: [b][d][j]
__device__ float2 g_S [NROWS];                    // (exp(s/2), exp(s/10))
__device__ float2 g_E [NROWS];                    // (exp(d/2), exp(d/10))

// ---------------------------------------------------------------------------
__device__ __forceinline__ uint32_t sm_u32(const void* p) {
    uint32_t a;
    asm("{ .reg .u64 t; cvta.to.shared.u64 t, %1; cvt.u32.u64 %0, t; }"
        : "=r"(a) : "l"(p));
    return a;
}
__device__ __forceinline__ void cp16(uint32_t dst, const void* src) {
    asm volatile("cp.async.cg.shared.global [%0], [%1], 16;"
                 :: "r"(dst), "l"(src));
}
__device__ __forceinline__ void cp_commit() {
    asm volatile("cp.async.commit_group;" ::: "memory");
}
template <int N>
__device__ __forceinline__ void cp_wait() {
    asm volatile("cp.async.wait_group %0;" :: "n"(N) : "memory");
}
__device__ __forceinline__ void ldsm_x4(uint32_t& r0, uint32_t& r1,
                                        uint32_t& r2, uint32_t& r3,
                                        uint32_t addr) {
    asm volatile("ldmatrix.sync.aligned.m8n8.x4.shared.b16 {%0,%1,%2,%3}, [%4];"
                 : "=r"(r0), "=r"(r1), "=r"(r2), "=r"(r3) : "r"(addr));
}
__device__ __forceinline__ void mma16816(float* c,
                                         uint32_t a0, uint32_t a1,
                                         uint32_t a2, uint32_t a3,
                                         uint32_t b0, uint32_t b1) {
    asm volatile("mma.sync.aligned.m16n8k16.row.col.f32.f16.f16.f32 "
                 "{%0,%1,%2,%3},{%4,%5,%6,%7},{%8,%9},{%0,%1,%2,%3};"
                 : "+f"(c[0]), "+f"(c[1]), "+f"(c[2]), "+f"(c[3])
                 : "r"(a0), "r"(a1), "r"(a2), "r"(a3), "r"(b0), "r"(b1));
}

// ---------------------------------------------------------------------------
// kW: W[k][n] fp32 -> g_WT[n][k] f16  (R10 version)
// ---------------------------------------------------------------------------
__global__ void __launch_bounds__(256) kW(const float* __restrict__ W) {
    __shared__ float sx[4][132];
    const int tid = threadIdx.x;
    const int kc0 = blockIdx.x * 4;
    if (tid < 128) {
        int kk = tid >> 5, d4 = (tid & 31) << 2;
        float4 v = *(const float4*)&W[(size_t)(kc0 + kk) * OUT_DIM + d4];
        sx[kk][d4 + 0] = v.x; sx[kk][d4 + 1] = v.y;
        sx[kk][d4 + 2] = v.z; sx[kk][d4 + 3] = v.w;
    }
    __syncthreads();
    if (tid < 128) {
        int d = tid;
        __half2 h0 = __floats2half2_rn(sx[0][d], sx[1][d]);
        __half2 h1 = __floats2half2_rn(sx[2][d], sx[3][d]);
        uint2 u; u.x = *(uint32_t*)&h0; u.y = *(uint32_t*)&h1;
        *(uint2*)&g_WT[(size_t)d * IN_DIM + kc0] = u;
    }
}

// ---------------------------------------------------------------------------
// k1: hT = W^T x^T via mma.sync f16 (M=d=128, N=j=128/CTA, K=256).
// Fused s/d reductions -> g_S / g_E exp tables. (R10 version, DRAM-floor.)
// ---------------------------------------------------------------------------
#define WT_PITCH_B 528
#define WT_BYTES   (OUT_DIM * WT_PITCH_B)
#define XS_BYTES   (128 * PADH * 2)
#define K1_DSM     (WT_BYTES + 2 * XS_BYTES)

__global__ void __launch_bounds__(256) k1_gemm(const float* __restrict__ x,
                                               const float* __restrict__ a_src,
                                               const float* __restrict__ a_dst) {
    extern __shared__ __align__(16) char dsm[];
    __shared__ float s_sm[128], d_sm[128];

    const int tid  = threadIdx.x;
    const int wid  = tid >> 5, lane = tid & 31;
    const int j0g  = blockIdx.x * 128;
    const int batch = j0g >> 12;
    const int jloc  = j0g & (N_ - 1);

    if (tid < 128) { s_sm[tid] = 0.f; d_sm[tid] = 0.f; }

    const uint32_t smb = sm_u32(dsm);

#pragma unroll
    for (int i = 0; i < 16; i++) {
        int f  = tid + 256 * i;
        int d  = f >> 5, ch = f & 31;
        cp16(smb + d * WT_PITCH_B + ch * 16, g_WT + (size_t)d * IN_DIM + ch * 8);
    }
    cp_commit();

    const int mh = wid & 1, nq = wid >> 1;
    const uint32_t aoff = (uint32_t)((mh * 64 + (lane & 15)) * WT_PITCH_B
                                     + ((lane >> 4) << 4));
    const uint32_t boff = (uint32_t)((nq * 32 + ((lane >> 4) << 3) + (lane & 7)) * (PADH * 2)
                                     + (((lane >> 3) & 1) << 4));

    float as0[4], as1[4], ad0[4], ad1[4];
#pragma unroll
    for (int mt = 0; mt < 4; mt++) {
        int d0 = mh * 64 + mt * 16 + (lane >> 2);
        as0[mt] = a_src[d0]; as1[mt] = a_src[d0 + 8];
        ad0[mt] = a_dst[d0]; ad1[mt] = a_dst[d0 + 8];
    }

    float c[16][4];
#pragma unroll
    for (int q = 0; q < 16; q++)
        c[q][0] = c[q][1] = c[q][2] = c[q][3] = 0.f;

    float4 XR[8];
    const int xj = tid >> 4, xk = (tid & 15) << 2;

#define LDG_X(CH)                                                             \
    do {                                                                      \
        _Pragma("unroll")                                                     \
        for (int i = 0; i < 8; i++)                                           \
            XR[i] = *(const float4*)&x[(size_t)(j0g + xj + i * 16) * IN_DIM   \
                                       + (CH) * 64 + xk];                     \
    } while (0)

    LDG_X(0);
    cp_wait<0>();
    __syncthreads();

    for (int ch = 0; ch < 4; ch++) {
        {
            char* xb = dsm + WT_BYTES + (ch & 1) * XS_BYTES;
#pragma unroll
            for (int i = 0; i < 8; i++) {
                __half2 p0 = __floats2half2_rn(XR[i].x, XR[i].y);
                __half2 p1 = __floats2half2_rn(XR[i].z, XR[i].w);
                uint2 u; u.x = *(uint32_t*)&p0; u.y = *(uint32_t*)&p1;
                *(uint2*)(xb + (xj + i * 16) * (PADH * 2) + xk * 2) = u;
            }
        }
        __syncthreads();
        if (ch < 3) LDG_X(ch + 1);

        const uint32_t ab = smb + aoff + ch * 128;
        const uint32_t bb = smb + WT_BYTES + (ch & 1) * XS_BYTES + boff;
#pragma unroll
        for (int ks = 0; ks < 4; ks++) {
            uint32_t b0, b1, b2, b3, b4, b5, b6, b7;
            ldsm_x4(b0, b1, b2, b3, bb + ks * 32);
            ldsm_x4(b4, b5, b6, b7, bb + 16 * (PADH * 2) + ks * 32);
#pragma unroll
            for (int mt = 0; mt < 4; mt++) {
                uint32_t a0, a1, a2, a3;
                ldsm_x4(a0, a1, a2, a3, ab + mt * 16 * WT_PITCH_B + ks * 32);
                mma16816(c[mt * 4 + 0], a0, a1, a2, a3, b0, b1);
                mma16816(c[mt * 4 + 1], a0, a1, a2, a3, b2, b3);
                mma16816(c[mt * 4 + 2], a0, a1, a2, a3, b4, b5);
                mma16816(c[mt * 4 + 3], a0, a1, a2, a3, b6, b7);
            }
        }
        __syncthreads();
    }

#pragma unroll
    for (int nt = 0; nt < 4; nt++) {
#pragma unroll
        for (int q = 0; q < 2; q++) {
            float ps = 0.f, pd = 0.f;
#pragma unroll
            for (int mt = 0; mt < 4; mt++) {
                const float* cf = c[mt * 4 + nt];
                ps += cf[q] * as0[mt] + cf[q + 2] * as1[mt];
                pd += cf[q] * ad0[mt] + cf[q + 2] * ad1[mt];
            }
#pragma unroll
            for (int o = 4; o < 32; o <<= 1) {
                ps += __shfl_xor_sync(0xffffffffu, ps, o);
                pd += __shfl_xor_sync(0xffffffffu, pd, o);
            }
            if (lane < 4) {
                int j = nq * 32 + nt * 8 + 2 * lane + q;
                atomicAdd(&s_sm[j], ps);
                atomicAdd(&d_sm[j], pd);
            }
        }
    }

#pragma unroll
    for (int mt = 0; mt < 4; mt++) {
        int dlo = mh * 64 + mt * 16 + (lane >> 2);
        int jg  = jloc + nq * 32 + 2 * (lane & 3);
#pragma unroll
        for (int nt = 0; nt < 4; nt++) {
            const float* cf = c[mt * 4 + nt];
            __half2 lo = __floats2half2_rn(cf[0], cf[1]);
            __half2 hi = __floats2half2_rn(cf[2], cf[3]);
            *(uint32_t*)&g_hT[((size_t)(batch * OUT_DIM + dlo)) * N_ + jg + nt * 8]
                = *(uint32_t*)&lo;
            *(uint32_t*)&g_hT[((size_t)(batch * OUT_DIM + dlo + 8)) * N_ + jg + nt * 8]
                = *(uint32_t*)&hi;
        }
    }

    __syncthreads();
    if (tid < 128) {
        float s = s_sm[tid], d = d_sm[tid];
        g_S[j0g + tid] = make_float2(expf(s * 0.5f), expf(s * 0.1f));
        g_E[j0g + tid] = make_float2(expf(d * 0.5f), expf(d * 0.1f));
    }
}

// ---------------------------------------------------------------------------
// kAB: fused masked-softmax weights + mma.sync f16 aggregation.
// RAGGED grid 148 (37 CTAs/batch: 34x7 + 3x6 m16-tiles) — all SMs busy,
// makespan 8 -> 7 tiles. Otherwise R10-verbatim: TJ=128, 2-stage cp.async h,
// 2-buffer alpha, 1 sync/tile, fp32 weight numerics.
// ---------------------------------------------------------------------------
#define HT2_B   (OUT_DIM * PITCH2)          // 34816
#define AL2_B   (MAXROWS * PITCH2)          // 30464
#define AL2_OFF (2 * HT2_B)                 // 69632
#define AB_DSM  (AL2_OFF + 2 * AL2_B)       // 130560

__global__ void __launch_bounds__(256, 1) kAB(const float* __restrict__ A,
                                              float* __restrict__ out) {
    extern __shared__ __align__(16) char dsm[];
    __shared__ float s_z[MAXROWS];

    const int tid  = threadIdx.x;
    const int wid  = tid >> 5, lane = tid & 31;
    const int batch = blockIdx.x / CPB;
    const int kk    = blockIdx.x % CPB;
    const int MT    = (kk < 34) ? 7 : 6;
    const int row0  = ((kk < 34) ? (7 * kk) : (6 * kk + 34)) * 16;
    const int WR    = MT * 2;                 // weight rows per warp
    const size_t rbase = (size_t)batch * N_;

    const uint32_t smb = sm_u32(dsm);
    const __half* hTb = g_hT + (size_t)batch * OUT_DIM * N_;

    // weight pass: warp covers rows wid*WR..+WR-1; lane covers cols 4l..4l+3
    float S1[MAXWR], S2[MAXWR], z[MAXWR];
#pragma unroll
    for (int r = 0; r < MAXWR; r++) {
        z[r] = 0.f; S1[r] = 0.f; S2[r] = 0.f;
        if (r < WR) {
            float2 sv = g_S[rbase + row0 + wid * WR + r];
            S1[r] = sv.x; S2[r] = sv.y;
        }
    }
    const float* Abase = A + (rbase + row0 + wid * WR) * (size_t)N_ + 4 * lane;

    // MMA split: mh = wid&1, nq = wid>>1 (32 d); warp m-tiles: mt = mh + 2*l
    const int mh = wid & 1, nq = wid >> 1;
    const uint32_t aoff_l = (uint32_t)(((lane & 15)) * PITCH2
                                       + ((lane >> 4) << 4));
    const uint32_t boff_l = (uint32_t)((nq * 32 + ((lane >> 4) << 3) + (lane & 7)) * PITCH2
                                       + (((lane >> 3) & 1) << 4));

    float c[16][4];
#pragma unroll
    for (int q = 0; q < 16; q++)
        c[q][0] = c[q][1] = c[q][2] = c[q][3] = 0.f;

    float4 AR[MAXWR];
    float4 EvA, EvB;

#define ISSUE_H(T, S)                                                         \
    do {                                                                      \
        const int jt_ = (T) * TJ2;                                            \
        uint32_t hd_ = smb + (S) * HT2_B;                                     \
        _Pragma("unroll")                                                     \
        for (int i = 0; i < 8; i++) {                                         \
            int f_ = tid + 256 * i;                                           \
            int dd_ = f_ >> 4, ch_ = f_ & 15;                                 \
            cp16(hd_ + dd_ * PITCH2 + ch_ * 16,                               \
                 hTb + (size_t)dd_ * N_ + jt_ + ch_ * 8);                     \
        }                                                                     \
        cp_commit();                                                          \
    } while (0)

#define LOAD_A(T)                                                             \
    do {                                                                      \
        EvA = *(const float4*)&g_E[rbase + (T) * TJ2 + 4 * lane];             \
        EvB = *(const float4*)&g_E[rbase + (T) * TJ2 + 4 * lane + 2];         \
        _Pragma("unroll")                                                     \
        for (int r = 0; r < MAXWR; r++)                                       \
            if (r < WR)                                                       \
                AR[r] = *(const float4*)(Abase + (size_t)r * N_ + (T) * TJ2); \
    } while (0)

#define WEIGHT(T)                                                             \
    do {                                                                      \
        __half* sal = (__half*)(dsm + AL2_OFF + ((T) & 1) * AL2_B);           \
        _Pragma("unroll")                                                     \
        for (int r = 0; r < MAXWR; r++) {                                     \
            if (r < WR) {                                                     \
                float4 av = AR[r];                                            \
                float w0 = fmaxf(S1[r] * EvA.x, S2[r] * EvA.y);               \
                float w1 = fmaxf(S1[r] * EvA.z, S2[r] * EvA.w);               \
                float w2 = fmaxf(S1[r] * EvB.x, S2[r] * EvB.y);               \
                float w3 = fmaxf(S1[r] * EvB.z, S2[r] * EvB.w);               \
                w0 = av.x >= 1e-9f ? w0 : 0.f;                                \
                w1 = av.y >= 1e-9f ? w1 : 0.f;                                \
                w2 = av.z >= 1e-9f ? w2 : 0.f;                                \
                w3 = av.w >= 1e-9f ? w3 : 0.f;                                \
                z[r] += (w0 + w1) + (w2 + w3);                                \
                __half2 p0 = __floats2half2_rn(w0, w1);                       \
                __half2 p1 = __floats2half2_rn(w2, w3);                       \
                uint2 u_; u_.x = *(uint32_t*)&p0; u_.y = *(uint32_t*)&p1;     \
                *(uint2*)&sal[(wid * WR + r) * PAD2 + 4 * lane] = u_;         \
            }                                                                 \
        }                                                                     \
    } while (0)

    // prologue
    LOAD_A(0);
    ISSUE_H(0, 0);
    WEIGHT(0);
    LOAD_A(1);

    for (int t = 0; t < NT2; t++) {
        cp_wait<0>();
        __syncthreads();   // h(t) staged, alpha(t) visible, WAR safe

        if (t + 1 < NT2) {
            ISSUE_H(t + 1, (t + 1) & 1);
            WEIGHT(t + 1);
            if (t + 2 < NT2) LOAD_A(t + 2);
        }

        const uint32_t ab = smb + AL2_OFF + (t & 1) * AL2_B + aoff_l;
        const uint32_t hb = smb + (t & 1) * HT2_B + boff_l;
#pragma unroll
        for (int ks = 0; ks < 8; ks++) {
            uint32_t b0, b1, b2, b3, b4, b5, b6, b7;
            ldsm_x4(b0, b1, b2, b3, hb + ks * 32);
            ldsm_x4(b4, b5, b6, b7, hb + 16 * PITCH2 + ks * 32);
#pragma unroll
            for (int l = 0; l < 4; l++) {
                const int mt = mh + 2 * l;
                if (mt < MT) {   // warp-uniform predicate
                    uint32_t a0, a1, a2, a3;
                    ldsm_x4(a0, a1, a2, a3, ab + mt * 16 * PITCH2 + ks * 32);
                    mma16816(c[l * 4 + 0], a0, a1, a2, a3, b0, b1);
                    mma16816(c[l * 4 + 1], a0, a1, a2, a3, b2, b3);
                    mma16816(c[l * 4 + 2], a0, a1, a2, a3, b4, b5);
                    mma16816(c[l * 4 + 3], a0, a1, a2, a3, b6, b7);
                }
            }
        }
    }

    // z row sums
#pragma unroll
    for (int r = 0; r < MAXWR; r++) {
        if (r < WR) {
            float zz = z[r];
#pragma unroll
            for (int o = 16; o; o >>= 1) zz += __shfl_xor_sync(0xffffffffu, zz, o);
            if (lane == 0) s_z[wid * WR + r] = zz;
        }
    }
    __syncthreads();

    // epilogue: warp (mh,nq); l-th m-tile = mh+2l
#pragma unroll
    for (int l = 0; l < 4; l++) {
        const int mt = mh + 2 * l;
        if (mt < MT) {
            const int rlo = mt * 16 + (lane >> 2);
            const float zlo = s_z[rlo], zhi = s_z[rlo + 8];
            const float invlo = zlo > 0.f ? 1.f / zlo : 0.f;
            const float invhi = zhi > 0.f ? 1.f / zhi : 0.f;
            float* olo = out + (rbase + row0 + rlo) * OUT_DIM + nq * 32 + 2 * (lane & 3);
            float* ohi = olo + 8 * OUT_DIM;
#pragma unroll
            for (int nt = 0; nt < 4; nt++) {
                const float* cf = c[l * 4 + nt];
                *(float2*)(olo + nt * 8) = make_float2(cf[0] * invlo, cf[1] * invlo);
                *(float2*)(ohi + nt * 8) = make_float2(cf[2] * invhi, cf[3] * invhi);
            }
        }
    }
}

// ---------------------------------------------------------------------------
extern "C" void kernel_launch(void* const* d_in, const int* in_sizes, int n_in,
                              void* d_out, int out_size) {
    const float* x     = (const float*)d_in[0];   // [4,4096,256]
    const float* A     = (const float*)d_in[1];   // [4,4096,4096]
    const float* W     = (const float*)d_in[2];   // [256,128]
    const float* a_src = (const float*)d_in[3];   // [128]
    const float* a_dst = (const float*)d_in[4];   // [128]
    float* out = (float*)d_out;                   // [4,4096,128]

    cudaFuncSetAttribute(k1_gemm, cudaFuncAttributeMaxDynamicSharedMemorySize,
                         K1_DSM);
    cudaFuncSetAttribute(kAB, cudaFuncAttributeMaxDynamicSharedMemorySize,
                         AB_DSM);

    kW     <<<64, 256>>>(W);
    k1_gemm<<<NROWS / 128, 256, K1_DSM>>>(x, a_src, a_dst);
    kAB    <<<B_ * CPB, 256, AB_DSM>>>(A, out);
    (void)in_sizes; (void)n_in; (void)out_size;
}

// round 17
// speedup vs baseline: 1.2588x; 1.0078x over previous
#include <cuda_runtime.h>
#include <cuda_fp16.h>
#include <math.h>
#include <stdint.h>

#define B_ 4
#define N_ 4096
#define IN_DIM 256
#define OUT_DIM 128
#define NROWS (B_ * N_)
#define PADH 72            // k1 smem half pitch (144B rows)
#define TJ2 128            // kAB j-tile
#define NT2 (N_ / TJ2)     // 32 tiles
#define PAD2 136           // kAB smem pitch in halves (272B)
#define PITCH2 272
#define CPB 37             // kAB CTAs per batch (34x7 + 3x6 m16-tiles)
#define MAXMT 7
#define MAXROWS (MAXMT * 16)   // 112
#define MAXWR (MAXMT * 2)      // 14 weight rows per warp

// Scratch (no cudaMalloc allowed)
__device__ __half g_WT[OUT_DIM * IN_DIM];         // W^T f16: [d][k]
__device__ __half g_hT[(size_t)B_ * OUT_DIM * N_];// f16 h^T: [b][d][j]
__device__ float2 g_S [NROWS];                    // (exp(s/2), exp(s/10))
__device__ float2 g_E [NROWS];                    // (exp(d/2), exp(d/10))

// ---------------------------------------------------------------------------
__device__ __forceinline__ uint32_t sm_u32(const void* p) {
    uint32_t a;
    asm("{ .reg .u64 t; cvta.to.shared.u64 t, %1; cvt.u32.u64 %0, t; }"
        : "=r"(a) : "l"(p));
    return a;
}
__device__ __forceinline__ void cp16(uint32_t dst, const void* src) {
    asm volatile("cp.async.cg.shared.global [%0], [%1], 16;"
                 :: "r"(dst), "l"(src));
}
__device__ __forceinline__ void cp_commit() {
    asm volatile("cp.async.commit_group;" ::: "memory");
}
template <int N>
__device__ __forceinline__ void cp_wait() {
    asm volatile("cp.async.wait_group %0;" :: "n"(N) : "memory");
}
__device__ __forceinline__ void ldsm_x4(uint32_t& r0, uint32_t& r1,
                                        uint32_t& r2, uint32_t& r3,
                                        uint32_t addr) {
    asm volatile("ldmatrix.sync.aligned.m8n8.x4.shared.b16 {%0,%1,%2,%3}, [%4];"
                 : "=r"(r0), "=r"(r1), "=r"(r2), "=r"(r3) : "r"(addr));
}
__device__ __forceinline__ void mma16816(float* c,
                                         uint32_t a0, uint32_t a1,
                                         uint32_t a2, uint32_t a3,
                                         uint32_t b0, uint32_t b1) {
    asm volatile("mma.sync.aligned.m16n8k16.row.col.f32.f16.f16.f32 "
                 "{%0,%1,%2,%3},{%4,%5,%6,%7},{%8,%9},{%0,%1,%2,%3};"
                 : "+f"(c[0]), "+f"(c[1]), "+f"(c[2]), "+f"(c[3])
                 : "r"(a0), "r"(a1), "r"(a2), "r"(a3), "r"(b0), "r"(b1));
}

// ---------------------------------------------------------------------------
// kW: W[k][n] fp32 -> g_WT[n][k] f16  (R10 version)
// ---------------------------------------------------------------------------
__global__ void __launch_bounds__(256) kW(const float* __restrict__ W) {
    __shared__ float sx[4][132];
    const int tid = threadIdx.x;
    const int kc0 = blockIdx.x * 4;
    if (tid < 128) {
        int kk = tid >> 5, d4 = (tid & 31) << 2;
        float4 v = *(const float4*)&W[(size_t)(kc0 + kk) * OUT_DIM + d4];
        sx[kk][d4 + 0] = v.x; sx[kk][d4 + 1] = v.y;
        sx[kk][d4 + 2] = v.z; sx[kk][d4 + 3] = v.w;
    }
    __syncthreads();
    if (tid < 128) {
        int d = tid;
        __half2 h0 = __floats2half2_rn(sx[0][d], sx[1][d]);
        __half2 h1 = __floats2half2_rn(sx[2][d], sx[3][d]);
        uint2 u; u.x = *(uint32_t*)&h0; u.y = *(uint32_t*)&h1;
        *(uint2*)&g_WT[(size_t)d * IN_DIM + kc0] = u;
    }
}

// ---------------------------------------------------------------------------
// k1: hT = W^T x^T via mma.sync f16 (M=d=128, N=j=128/CTA, K=256).
// Fused s/d reductions -> g_S / g_E exp tables. (R10 version, DRAM-floor.)
// ---------------------------------------------------------------------------
#define WT_PITCH_B 528
#define WT_BYTES   (OUT_DIM * WT_PITCH_B)
#define XS_BYTES   (128 * PADH * 2)
#define K1_DSM     (WT_BYTES + 2 * XS_BYTES)

__global__ void __launch_bounds__(256) k1_gemm(const float* __restrict__ x,
                                               const float* __restrict__ a_src,
                                               const float* __restrict__ a_dst) {
    extern __shared__ __align__(16) char dsm[];
    __shared__ float s_sm[128], d_sm[128];

    const int tid  = threadIdx.x;
    const int wid  = tid >> 5, lane = tid & 31;
    const int j0g  = blockIdx.x * 128;
    const int batch = j0g >> 12;
    const int jloc  = j0g & (N_ - 1);

    if (tid < 128) { s_sm[tid] = 0.f; d_sm[tid] = 0.f; }

    const uint32_t smb = sm_u32(dsm);

#pragma unroll
    for (int i = 0; i < 16; i++) {
        int f  = tid + 256 * i;
        int d  = f >> 5, ch = f & 31;
        cp16(smb + d * WT_PITCH_B + ch * 16, g_WT + (size_t)d * IN_DIM + ch * 8);
    }
    cp_commit();

    const int mh = wid & 1, nq = wid >> 1;
    const uint32_t aoff = (uint32_t)((mh * 64 + (lane & 15)) * WT_PITCH_B
                                     + ((lane >> 4) << 4));
    const uint32_t boff = (uint32_t)((nq * 32 + ((lane >> 4) << 3) + (lane & 7)) * (PADH * 2)
                                     + (((lane >> 3) & 1) << 4));

    float as0[4], as1[4], ad0[4], ad1[4];
#pragma unroll
    for (int mt = 0; mt < 4; mt++) {
        int d0 = mh * 64 + mt * 16 + (lane >> 2);
        as0[mt] = a_src[d0]; as1[mt] = a_src[d0 + 8];
        ad0[mt] = a_dst[d0]; ad1[mt] = a_dst[d0 + 8];
    }

    float c[16][4];
#pragma unroll
    for (int q = 0; q < 16; q++)
        c[q][0] = c[q][1] = c[q][2] = c[q][3] = 0.f;

    float4 XR[8];
    const int xj = tid >> 4, xk = (tid & 15) << 2;

#define LDG_X(CH)                                                             \
    do {                                                                      \
        _Pragma("unroll")                                                     \
        for (int i = 0; i < 8; i++)                                           \
            XR[i] = *(const float4*)&x[(size_t)(j0g + xj + i * 16) * IN_DIM   \
                                       + (CH) * 64 + xk];                     \
    } while (0)

    LDG_X(0);
    cp_wait<0>();
    __syncthreads();

    for (int ch = 0; ch < 4; ch++) {
        {
            char* xb = dsm + WT_BYTES + (ch & 1) * XS_BYTES;
#pragma unroll
            for (int i = 0; i < 8; i++) {
                __half2 p0 = __floats2half2_rn(XR[i].x, XR[i].y);
                __half2 p1 = __floats2half2_rn(XR[i].z, XR[i].w);
                uint2 u; u.x = *(uint32_t*)&p0; u.y = *(uint32_t*)&p1;
                *(uint2*)(xb + (xj + i * 16) * (PADH * 2) + xk * 2) = u;
            }
        }
        __syncthreads();
        if (ch < 3) LDG_X(ch + 1);

        const uint32_t ab = smb + aoff + ch * 128;
        const uint32_t bb = smb + WT_BYTES + (ch & 1) * XS_BYTES + boff;
#pragma unroll
        for (int ks = 0; ks < 4; ks++) {
            uint32_t b0, b1, b2, b3, b4, b5, b6, b7;
            ldsm_x4(b0, b1, b2, b3, bb + ks * 32);
            ldsm_x4(b4, b5, b6, b7, bb + 16 * (PADH * 2) + ks * 32);
#pragma unroll
            for (int mt = 0; mt < 4; mt++) {
                uint32_t a0, a1, a2, a3;
                ldsm_x4(a0, a1, a2, a3, ab + mt * 16 * WT_PITCH_B + ks * 32);
                mma16816(c[mt * 4 + 0], a0, a1, a2, a3, b0, b1);
                mma16816(c[mt * 4 + 1], a0, a1, a2, a3, b2, b3);
                mma16816(c[mt * 4 + 2], a0, a1, a2, a3, b4, b5);
                mma16816(c[mt * 4 + 3], a0, a1, a2, a3, b6, b7);
            }
        }
        __syncthreads();
    }

#pragma unroll
    for (int nt = 0; nt < 4; nt++) {
#pragma unroll
        for (int q = 0; q < 2; q++) {
            float ps = 0.f, pd = 0.f;
#pragma unroll
            for (int mt = 0; mt < 4; mt++) {
                const float* cf = c[mt * 4 + nt];
                ps += cf[q] * as0[mt] + cf[q + 2] * as1[mt];
                pd += cf[q] * ad0[mt] + cf[q + 2] * ad1[mt];
            }
#pragma unroll
            for (int o = 4; o < 32; o <<= 1) {
                ps += __shfl_xor_sync(0xffffffffu, ps, o);
                pd += __shfl_xor_sync(0xffffffffu, pd, o);
            }
            if (lane < 4) {
                int j = nq * 32 + nt * 8 + 2 * lane + q;
                atomicAdd(&s_sm[j], ps);
                atomicAdd(&d_sm[j], pd);
            }
        }
    }

#pragma unroll
    for (int mt = 0; mt < 4; mt++) {
        int dlo = mh * 64 + mt * 16 + (lane >> 2);
        int jg  = jloc + nq * 32 + 2 * (lane & 3);
#pragma unroll
        for (int nt = 0; nt < 4; nt++) {
            const float* cf = c[mt * 4 + nt];
            __half2 lo = __floats2half2_rn(cf[0], cf[1]);
            __half2 hi = __floats2half2_rn(cf[2], cf[3]);
            *(uint32_t*)&g_hT[((size_t)(batch * OUT_DIM + dlo)) * N_ + jg + nt * 8]
                = *(uint32_t*)&lo;
            *(uint32_t*)&g_hT[((size_t)(batch * OUT_DIM + dlo + 8)) * N_ + jg + nt * 8]
                = *(uint32_t*)&hi;
        }
    }

    __syncthreads();
    if (tid < 128) {
        float s = s_sm[tid], d = d_sm[tid];
        g_S[j0g + tid] = make_float2(expf(s * 0.5f), expf(s * 0.1f));
        g_E[j0g + tid] = make_float2(expf(d * 0.5f), expf(d * 0.1f));
    }
}

// ---------------------------------------------------------------------------
// kAB: fused masked-softmax weights + mma.sync f16 aggregation.
// Ragged grid 148 (34x7 + 3x6 m16-tiles/batch). NEW vs R16:
//  - mh = wid>>2, nq = wid&3: each SMSP gets one mh0 + one mh1 warp ->
//    per-SMSP HMMA load balanced (was 4:3 skewed onto SMSPs 0/2).
//  - stagger: mh0 warps WEIGHT->MMA, mh1 warps MMA->WEIGHT, so the
//    co-resident warp's HMMAs cover the other's scalar window.
// Numerics identical to R10/R16.
// ---------------------------------------------------------------------------
#define HT2_B   (OUT_DIM * PITCH2)          // 34816
#define AL2_B   (MAXROWS * PITCH2)          // 30464
#define AL2_OFF (2 * HT2_B)                 // 69632
#define AB_DSM  (AL2_OFF + 2 * AL2_B)       // 130560

__global__ void __launch_bounds__(256, 1) kAB(const float* __restrict__ A,
                                              float* __restrict__ out) {
    extern __shared__ __align__(16) char dsm[];
    __shared__ float s_z[MAXROWS];

    const int tid  = threadIdx.x;
    const int wid  = tid >> 5, lane = tid & 31;
    const int batch = blockIdx.x / CPB;
    const int kk    = blockIdx.x % CPB;
    const int MT    = (kk < 34) ? 7 : 6;
    const int row0  = ((kk < 34) ? (7 * kk) : (6 * kk + 34)) * 16;
    const int WR    = MT * 2;                 // weight rows per warp
    const size_t rbase = (size_t)batch * N_;

    const uint32_t smb = sm_u32(dsm);
    const __half* hTb = g_hT + (size_t)batch * OUT_DIM * N_;

    // weight pass: warp covers rows wid*WR..+WR-1; lane covers cols 4l..4l+3
    float S1[MAXWR], S2[MAXWR], z[MAXWR];
#pragma unroll
    for (int r = 0; r < MAXWR; r++) {
        z[r] = 0.f; S1[r] = 0.f; S2[r] = 0.f;
        if (r < WR) {
            float2 sv = g_S[rbase + row0 + wid * WR + r];
            S1[r] = sv.x; S2[r] = sv.y;
        }
    }
    const float* Abase = A + (rbase + row0 + wid * WR) * (size_t)N_ + 4 * lane;

    // MMA split: mh = wid>>2 (SMSP-balanced), nq = wid&3 (32 d each).
    // Warp m-tiles: mt = 2*l + mh.
    const int mh = wid >> 2, nq = wid & 3;
    const uint32_t aoff_l = (uint32_t)(((lane & 15)) * PITCH2
                                       + ((lane >> 4) << 4));
    const uint32_t boff_l = (uint32_t)((nq * 32 + ((lane >> 4) << 3) + (lane & 7)) * PITCH2
                                       + (((lane >> 3) & 1) << 4));

    float c[16][4];
#pragma unroll
    for (int q = 0; q < 16; q++)
        c[q][0] = c[q][1] = c[q][2] = c[q][3] = 0.f;

    float4 AR[MAXWR];
    float4 EvA, EvB;

#define ISSUE_H(T, S)                                                         \
    do {                                                                      \
        const int jt_ = (T) * TJ2;                                            \
        uint32_t hd_ = smb + (S) * HT2_B;                                     \
        _Pragma("unroll")                                                     \
        for (int i = 0; i < 8; i++) {                                         \
            int f_ = tid + 256 * i;                                           \
            int dd_ = f_ >> 4, ch_ = f_ & 15;                                 \
            cp16(hd_ + dd_ * PITCH2 + ch_ * 16,                               \
                 hTb + (size_t)dd_ * N_ + jt_ + ch_ * 8);                     \
        }                                                                     \
        cp_commit();                                                          \
    } while (0)

#define LOAD_A(T)                                                             \
    do {                                                                      \
        EvA = *(const float4*)&g_E[rbase + (T) * TJ2 + 4 * lane];             \
        EvB = *(const float4*)&g_E[rbase + (T) * TJ2 + 4 * lane + 2];         \
        _Pragma("unroll")                                                     \
        for (int r = 0; r < MAXWR; r++)                                       \
            if (r < WR)                                                       \
                AR[r] = *(const float4*)(Abase + (size_t)r * N_ + (T) * TJ2); \
    } while (0)

#define WEIGHT(T)                                                             \
    do {                                                                      \
        __half* sal = (__half*)(dsm + AL2_OFF + ((T) & 1) * AL2_B);           \
        _Pragma("unroll")                                                     \
        for (int r = 0; r < MAXWR; r++) {                                     \
            if (r < WR) {                                                     \
                float4 av = AR[r];                                            \
                float w0 = fmaxf(S1[r] * EvA.x, S2[r] * EvA.y);               \
                float w1 = fmaxf(S1[r] * EvA.z, S2[r] * EvA.w);               \
                float w2 = fmaxf(S1[r] * EvB.x, S2[r] * EvB.y);               \
                float w3 = fmaxf(S1[r] * EvB.z, S2[r] * EvB.w);               \
                w0 = av.x >= 1e-9f ? w0 : 0.f;                                \
                w1 = av.y >= 1e-9f ? w1 : 0.f;                                \
                w2 = av.z >= 1e-9f ? w2 : 0.f;                                \
                w3 = av.w >= 1e-9f ? w3 : 0.f;                                \
                z[r] += (w0 + w1) + (w2 + w3);                                \
                __half2 p0 = __floats2half2_rn(w0, w1);                       \
                __half2 p1 = __floats2half2_rn(w2, w3);                       \
                uint2 u_; u_.x = *(uint32_t*)&p0; u_.y = *(uint32_t*)&p1;     \
                *(uint2*)&sal[(wid * WR + r) * PAD2 + 4 * lane] = u_;         \
            }                                                                 \
        }                                                                     \
    } while (0)

#define PRODUCE(T_NEXT, T_PRE)                                                \
    do {                                                                      \
        ISSUE_H((T_NEXT), (T_NEXT) & 1);                                      \
        WEIGHT(T_NEXT);                                                       \
        if ((T_PRE) < NT2) LOAD_A(T_PRE);                                     \
    } while (0)

#define MMA_BODY(AB, HB)                                                      \
    do {                                                                      \
        _Pragma("unroll")                                                     \
        for (int ks = 0; ks < 8; ks++) {                                      \
            uint32_t b0, b1, b2, b3, b4, b5, b6, b7;                          \
            ldsm_x4(b0, b1, b2, b3, (HB) + ks * 32);                          \
            ldsm_x4(b4, b5, b6, b7, (HB) + 16 * PITCH2 + ks * 32);            \
            _Pragma("unroll")                                                 \
            for (int l = 0; l < 4; l++) {                                     \
                const int mt = 2 * l + mh;                                    \
                if (mt < MT) {   /* warp-uniform predicate */                 \
                    uint32_t a0, a1, a2, a3;                                  \
                    ldsm_x4(a0, a1, a2, a3, (AB) + mt * 16 * PITCH2 + ks * 32);\
                    mma16816(c[l * 4 + 0], a0, a1, a2, a3, b0, b1);           \
                    mma16816(c[l * 4 + 1], a0, a1, a2, a3, b2, b3);           \
                    mma16816(c[l * 4 + 2], a0, a1, a2, a3, b4, b5);           \
                    mma16816(c[l * 4 + 3], a0, a1, a2, a3, b6, b7);           \
                }                                                             \
            }                                                                 \
        }                                                                     \
    } while (0)

    // prologue
    LOAD_A(0);
    ISSUE_H(0, 0);
    WEIGHT(0);
    LOAD_A(1);

    for (int t = 0; t < NT2; t++) {
        cp_wait<0>();
        __syncthreads();   // h(t) staged, alpha(t) visible, WAR safe

        const bool doW = (t + 1 < NT2);
        const uint32_t ab = smb + AL2_OFF + (t & 1) * AL2_B + aoff_l;
        const uint32_t hb = smb + (t & 1) * HT2_B + boff_l;

        if (mh == 0) {
            if (doW) PRODUCE(t + 1, t + 2);
            MMA_BODY(ab, hb);
        } else {
            MMA_BODY(ab, hb);
            if (doW) PRODUCE(t + 1, t + 2);
        }
    }

    // z row sums
#pragma unroll
    for (int r = 0; r < MAXWR; r++) {
        if (r < WR) {
            float zz = z[r];
#pragma unroll
            for (int o = 16; o; o >>= 1) zz += __shfl_xor_sync(0xffffffffu, zz, o);
            if (lane == 0) s_z[wid * WR + r] = zz;
        }
    }
    __syncthreads();

    // epilogue: warp (mh,nq); l-th m-tile = 2l+mh
#pragma unroll
    for (int l = 0; l < 4; l++) {
        const int mt = 2 * l + mh;
        if (mt < MT) {
            const int rlo = mt * 16 + (lane >> 2);
            const float zlo = s_z[rlo], zhi = s_z[rlo + 8];
            const float invlo = zlo > 0.f ? 1.f / zlo : 0.f;
            const float invhi = zhi > 0.f ? 1.f / zhi : 0.f;
            float* olo = out + (rbase + row0 + rlo) * OUT_DIM + nq * 32 + 2 * (lane & 3);
            float* ohi = olo + 8 * OUT_DIM;
#pragma unroll
            for (int nt = 0; nt < 4; nt++) {
                const float* cf = c[l * 4 + nt];
                *(float2*)(olo + nt * 8) = make_float2(cf[0] * invlo, cf[1] * invlo);
                *(float2*)(ohi + nt * 8) = make_float2(cf[2] * invhi, cf[3] * invhi);
            }
        }
    }
}

// ---------------------------------------------------------------------------
extern "C" void kernel_launch(void* const* d_in, const int* in_sizes, int n_in,
                              void* d_out, int out_size) {
    const float* x     = (const float*)d_in[0];   // [4,4096,256]
    const float* A     = (const float*)d_in[1];   // [4,4096,4096]
    const float* W     = (const float*)d_in[2];   // [256,128]
    const float* a_src = (const float*)d_in[3];   // [128]
    const float* a_dst = (const float*)d_in[4];   // [128]
    float* out = (float*)d_out;                   // [4,4096,128]

    cudaFuncSetAttribute(k1_gemm, cudaFuncAttributeMaxDynamicSharedMemorySize,
                         K1_DSM);
    cudaFuncSetAttribute(kAB, cudaFuncAttributeMaxDynamicSharedMemorySize,
                         AB_DSM);

    kW     <<<64, 256>>>(W);
    k1_gemm<<<NROWS / 128, 256, K1_DSM>>>(x, a_src, a_dst);
    kAB    <<<B_ * CPB, 256, AB_DSM>>>(A, out);
    (void)in_sizes; (void)n_in; (void)out_size;
}